// round 7
// baseline (speedup 1.0000x reference)
#include <cuda_runtime.h>
#include <cuda_bf16.h>
#include <cstdint>

#define NMAX 100000
#define EMAX 1600000
#define HD   128
#define BMAX 256
#define OMAX 32

// ---------------- static scratch ----------------
__device__ float    g_z   [NMAX * HD];     // pre-BN layer output
__device__ float    g_agg [NMAX * HD];
__device__ float    g_z1  [NMAX * HD];
__device__ float    g_stats[2 * HD];
__device__ float    g_ssum[BMAX * HD];
__device__ unsigned g_smax[BMAX * HD];
__device__ int      g_cnt [BMAX];
__device__ float    g_graph[BMAX * 384];
__device__ float    g_oe  [BMAX * OMAX * HD];
__device__ float    g_comb[BMAX * OMAX * 512];
__device__ float    g_s1  [BMAX * OMAX * HD];
__device__ float    g_s2  [BMAX * OMAX * 64];
__device__ uint4    g_wfrag[46080];
// CSR
__device__ int      g_deg   [NMAX];
__device__ int      g_rowptr[NMAX + 1];
__device__ int      g_cursor[NMAX];
__device__ int      g_ssrc  [EMAX];
__device__ int      g_bsum  [256];
__device__ int      g_boff  [256];

#define MMA_BF16(c, a, b0, b1) \
    asm volatile("mma.sync.aligned.m16n8k16.row.col.f32.bf16.bf16.f32 " \
        "{%0,%1,%2,%3}, {%4,%5,%6,%7}, {%8,%9}, {%0,%1,%2,%3};" \
        : "+f"((c)[0]), "+f"((c)[1]), "+f"((c)[2]), "+f"((c)[3]) \
        : "r"((a)[0]), "r"((a)[1]), "r"((a)[2]), "r"((a)[3]), "r"(b0), "r"(b1))

__device__ __forceinline__ void cvt_hilo(float2 v, uint32_t& hi, uint32_t& lo) {
    __nv_bfloat162 h = __float22bfloat162_rn(v);
    float hx = __bfloat162float(h.x), hy = __bfloat162float(h.y);
    __nv_bfloat162 l = __float22bfloat162_rn(make_float2(v.x - hx, v.y - hy));
    hi = *(uint32_t*)&h;
    lo = *(uint32_t*)&l;
}

__device__ __forceinline__ unsigned fenc(float f) {
    unsigned u = __float_as_uint(f);
    return (u & 0x80000000u) ? ~u : (u | 0x80000000u);
}
__device__ __forceinline__ float fdec(unsigned u) {
    unsigned b = (u & 0x80000000u) ? (u & 0x7FFFFFFFu) : ~u;
    return __uint_as_float(b);
}
#define NEG_INF __uint_as_float(0xff800000u)

// ---------------- weight prep (fragment order) ----------------
__global__ void prep_k(const float* __restrict__ gW1, const float* __restrict__ gW2,
                       const float* __restrict__ oW1f, const float* __restrict__ oW2f,
                       const float* __restrict__ sW1f) {
    int idx = blockIdx.x * blockDim.x + threadIdx.x;
    if (idx >= 184320) return;
    const float* W; int el;
    if (idx < 98304) {
        int m = idx / 16384; el = idx % 16384;
        W = (m < 3) ? gW1 + (size_t)m * 16384 : gW2 + (size_t)(m - 3) * 16384;
    } else if (idx < 102400) { el = idx - 98304;  W = oW1f; }
    else if   (idx < 118784) { el = idx - 102400; W = oW2f; }
    else                     { el = idx - 118784; W = sW1f; }
    int ks = el >> 11;
    int rem = el & 2047;
    int ntile = rem >> 7;
    int lane = (rem & 127) >> 2;
    int q = rem & 3;
    int n = ntile * 8 + (lane >> 2);
    int k = ks * 16 + (lane & 3) * 2 + ((q & 1) ? 8 : 0);
    float v0 = W[(size_t)k * 128 + n];
    float v1 = W[(size_t)(k + 1) * 128 + n];
    uint32_t r;
    __nv_bfloat16 h0 = __float2bfloat16(v0), h1 = __float2bfloat16(v1);
    if (q < 2) {
        r = ((uint32_t)__bfloat16_as_ushort(h1) << 16) | __bfloat16_as_ushort(h0);
    } else {
        __nv_bfloat16 l0 = __float2bfloat16(v0 - __bfloat162float(h0));
        __nv_bfloat16 l1 = __float2bfloat16(v1 - __bfloat162float(h1));
        r = ((uint32_t)__bfloat16_as_ushort(l1) << 16) | __bfloat16_as_ushort(l0);
    }
    ((uint32_t*)g_wfrag)[idx] = r;
}

// ---------------- CSR build ----------------
__global__ void zero_deg_k(int n) {
    int i = blockIdx.x * blockDim.x + threadIdx.x;
    if (i < n) g_deg[i] = 0;
}
__global__ void hist_k(const int* __restrict__ ei, int E) {
    int i = blockIdx.x * blockDim.x + threadIdx.x;
    if (i < E) atomicAdd(&g_deg[__ldg(ei + E + i)], 1);
}
__global__ void partial_k(int n) {
    __shared__ int sd[256];
    int C = (n + 255) / 256;
    int start = blockIdx.x * C, end = min(start + C, n);
    int s = 0;
    for (int i = start + threadIdx.x; i < end; i += 256) s += g_deg[i];
    sd[threadIdx.x] = s;
    __syncthreads();
    for (int o = 128; o > 0; o >>= 1) {
        if (threadIdx.x < o) sd[threadIdx.x] += sd[threadIdx.x + o];
        __syncthreads();
    }
    if (threadIdx.x == 0) g_bsum[blockIdx.x] = sd[0];
}
__global__ void scanb_k() {
    __shared__ int sd[256];
    int t = threadIdx.x;
    sd[t] = g_bsum[t];
    __syncthreads();
    for (int o = 1; o < 256; o <<= 1) {
        int v = (t >= o) ? sd[t - o] : 0;
        __syncthreads();
        sd[t] += v;
        __syncthreads();
    }
    g_boff[t] = sd[t] - g_bsum[t];
}
__global__ void rowptr_k(int n, int E) {
    __shared__ int sd[256];
    int C = (n + 255) / 256;
    int start = blockIdx.x * C, end = min(start + C, n);
    int off = g_boff[blockIdx.x];
    for (int base = start; base < end; base += 256) {
        int i = base + threadIdx.x;
        int d = (i < end) ? g_deg[i] : 0;
        sd[threadIdx.x] = d;
        __syncthreads();
        for (int o = 1; o < 256; o <<= 1) {
            int v = (threadIdx.x >= o) ? sd[threadIdx.x - o] : 0;
            __syncthreads();
            sd[threadIdx.x] += v;
            __syncthreads();
        }
        if (i < end) {
            int ex = off + sd[threadIdx.x] - d;
            g_rowptr[i] = ex;
            g_cursor[i] = ex;
        }
        int tot = sd[255];
        __syncthreads();
        off += tot;
    }
    if (blockIdx.x == 255 && threadIdx.x == 0) g_rowptr[n] = E;
}
__global__ void fill_k(const int* __restrict__ ei, int E) {
    int i = blockIdx.x * blockDim.x + threadIdx.x;
    if (i >= E) return;
    int s = __ldg(ei + i);
    int d = __ldg(ei + E + i);
    int pos = atomicAdd(&g_cursor[d], 1);
    g_ssrc[pos] = s;
}

// ---------------- gather with fused BN(+relu): agg[d] = Σ f(z[src]) + f(z[d]) ----------------
// Layer 0: useBn=0, doRelu=0 -> pure aggregation of raw x.
__global__ void gather_k(const float* __restrict__ z, float* __restrict__ agg,
                         const float* __restrict__ gamma, const float* __restrict__ beta,
                         int n, int useBn, int doRelu, float invN) {
    __shared__ float sa[128], sb[128];
    if (threadIdx.x < 128) {
        if (useBn) {
            float mu = g_stats[threadIdx.x] * invN;
            float q = g_stats[128 + threadIdx.x] * invN;
            float var = q - mu * mu;
            float aa = gamma[threadIdx.x] * rsqrtf(var + 1e-5f);
            sa[threadIdx.x] = aa;
            sb[threadIdx.x] = beta[threadIdx.x] - mu * aa;
        } else {
            sa[threadIdx.x] = 1.f;
            sb[threadIdx.x] = 0.f;
        }
    }
    __syncthreads();
    int wid = blockIdx.x * (blockDim.x >> 5) + (threadIdx.x >> 5);
    int lane = threadIdx.x & 31;
    if (wid >= n) return;
    float4 a4 = *(float4*)&sa[lane * 4];
    float4 b4 = *(float4*)&sb[lane * 4];

    auto xf = [&](float4 v) {
        float4 r;
        r.x = a4.x * v.x + b4.x; r.y = a4.y * v.y + b4.y;
        r.z = a4.z * v.z + b4.z; r.w = a4.w * v.w + b4.w;
        if (doRelu) {
            r.x = fmaxf(r.x, 0.f); r.y = fmaxf(r.y, 0.f);
            r.z = fmaxf(r.z, 0.f); r.w = fmaxf(r.w, 0.f);
        }
        return r;
    };

    int beg = __ldg(&g_rowptr[wid]);
    int end = __ldg(&g_rowptr[wid + 1]);
    const float4* z4 = (const float4*)z;
    float4 acc = xf(__ldg(z4 + (size_t)wid * 32 + lane));
    int j = beg;
    for (; j + 4 <= end; j += 4) {
        int s0 = __ldg(&g_ssrc[j]);
        int s1 = __ldg(&g_ssrc[j + 1]);
        int s2 = __ldg(&g_ssrc[j + 2]);
        int s3 = __ldg(&g_ssrc[j + 3]);
        float4 v0 = xf(__ldg(z4 + (size_t)s0 * 32 + lane));
        float4 v1 = xf(__ldg(z4 + (size_t)s1 * 32 + lane));
        float4 v2 = xf(__ldg(z4 + (size_t)s2 * 32 + lane));
        float4 v3 = xf(__ldg(z4 + (size_t)s3 * 32 + lane));
        acc.x += v0.x + v1.x + v2.x + v3.x;
        acc.y += v0.y + v1.y + v2.y + v3.y;
        acc.z += v0.z + v1.z + v2.z + v3.z;
        acc.w += v0.w + v1.w + v2.w + v3.w;
    }
    for (; j < end; j++) {
        int s = __ldg(&g_ssrc[j]);
        float4 v = xf(__ldg(z4 + (size_t)s * 32 + lane));
        acc.x += v.x; acc.y += v.y; acc.z += v.z; acc.w += v.w;
    }
    ((float4*)agg)[(size_t)wid * 32 + lane] = acc;
}

// ---------------- mma GEMM: 128 rows/block, 32 rows/warp, no smem mainloop ----------------
// statsMode: 0 = none, 1 = zero g_stats (block 0), 2 = accumulate column sums/sumsq
__global__ void __launch_bounds__(128) gemm_f(
    const float* __restrict__ A, const uint4* __restrict__ wf,
    const float* __restrict__ bias, float* __restrict__ out,
    int M, int K, int relu, int statsMode) {
    __shared__ float sred[256];
    const int tid = threadIdx.x;
    const int lane = tid & 31;
    const int warp = tid >> 5;
    const int fr = lane >> 2;
    const int c2 = (lane & 3) * 2;
    const int rb = blockIdx.x * 128 + warp * 32;

    if (statsMode == 1 && blockIdx.x == 0 && tid < 128) {
        g_stats[tid] = 0.f;
        g_stats[tid + 128] = 0.f;
    }

    int r[4]; bool vld[4];
#pragma unroll
    for (int g = 0; g < 4; g++) {
        r[g] = rb + g * 8 + fr;
        vld[g] = r[g] < M;
    }

    float acc[16][8];
#pragma unroll
    for (int nt = 0; nt < 16; nt++)
#pragma unroll
        for (int i = 0; i < 8; i++) acc[nt][i] = 0.f;

    const uint4* wp = wf + lane;
    const int nks = K >> 4;
    const float2 z2 = make_float2(0.f, 0.f);
    for (int ks = 0; ks < nks; ks++) {
        uint32_t ah[8], al[8];
#pragma unroll
        for (int g = 0; g < 4; g++) {
            const float* ap = A + (size_t)r[g] * K + ks * 16 + c2;
            float2 x0 = vld[g] ? __ldg((const float2*)ap)       : z2;
            float2 x1 = vld[g] ? __ldg((const float2*)(ap + 8)) : z2;
            int bi = (g >> 1) * 4 + (g & 1);
            cvt_hilo(x0, ah[bi], al[bi]);
            cvt_hilo(x1, ah[bi + 2], al[bi + 2]);
        }
        const uint4* wk = wp + ks * 512;
#pragma unroll
        for (int nt = 0; nt < 16; nt++) {
            uint4 w = __ldg(wk + nt * 32);
            MMA_BF16(acc[nt],     ah,     w.x, w.y);
            MMA_BF16(acc[nt] + 4, ah + 4, w.x, w.y);
            MMA_BF16(acc[nt],     ah,     w.z, w.w);
            MMA_BF16(acc[nt] + 4, ah + 4, w.z, w.w);
            MMA_BF16(acc[nt],     al,     w.x, w.y);
            MMA_BF16(acc[nt] + 4, al + 4, w.x, w.y);
        }
    }

    if (statsMode == 2) {
        sred[tid] = 0.f;
        sred[tid + 128] = 0.f;
        __syncthreads();
    }

#pragma unroll
    for (int nt = 0; nt < 16; nt++) {
        int c = nt * 8 + c2;
        float bx = __ldg(bias + c), by = __ldg(bias + c + 1);
        float s0 = 0.f, q0 = 0.f, s1 = 0.f, q1 = 0.f;
#pragma unroll
        for (int p = 0; p < 4; p++) {
            float wx = acc[nt][p * 2] + bx;
            float wy = acc[nt][p * 2 + 1] + by;
            if (relu) { wx = fmaxf(wx, 0.f); wy = fmaxf(wy, 0.f); }
            if (vld[p]) {
                *(float2*)(out + (size_t)r[p] * 128 + c) = make_float2(wx, wy);
                s0 += wx; q0 += wx * wx; s1 += wy; q1 += wy * wy;
            }
        }
        if (statsMode == 2) {
#pragma unroll
            for (int o = 4; o < 32; o <<= 1) {
                s0 += __shfl_xor_sync(0xffffffffu, s0, o);
                s1 += __shfl_xor_sync(0xffffffffu, s1, o);
                q0 += __shfl_xor_sync(0xffffffffu, q0, o);
                q1 += __shfl_xor_sync(0xffffffffu, q1, o);
            }
            if (lane < 4) {
                atomicAdd(&sred[c], s0);
                atomicAdd(&sred[c + 1], s1);
                atomicAdd(&sred[128 + c], q0);
                atomicAdd(&sred[128 + c + 1], q1);
            }
        }
    }
    if (statsMode == 2) {
        __syncthreads();
        atomicAdd(&g_stats[tid], sred[tid]);
        atomicAdd(&g_stats[tid + 128], sred[tid + 128]);
    }
}

// ---------------- pooling with fused BN (no relu on last layer) ----------------
__global__ void pool_init_k(int B) {
    int i = blockIdx.x * blockDim.x + threadIdx.x;
    if (i < B * HD) { g_ssum[i] = 0.f; g_smax[i] = 0x007FFFFFu; }
    if (i < B) g_cnt[i] = 0;
}
__global__ void pool_k(const float* __restrict__ z, const int* __restrict__ batch,
                       const float* __restrict__ gamma, const float* __restrict__ beta,
                       int n, float invN) {
    const int t = threadIdx.x;                // 128 threads, one per feature
    float mu = g_stats[t] * invN;
    float q = g_stats[128 + t] * invN;
    float var = q - mu * mu;
    float aa = gamma[t] * rsqrtf(var + 1e-5f);
    float bb = beta[t] - mu * aa;

    int start = blockIdx.x * 256;
    int end = min(start + 256, n);
    if (start >= end) return;
    int cur = __ldg(batch + start);
    float s = 0.f, m = NEG_INF;
    int c = 0;
    for (int v0 = start; v0 < end; v0 += 8) {
        float vals[8]; int bs[8];
        int mm = min(8, end - v0);
#pragma unroll
        for (int k = 0; k < 8; k++) {
            if (k < mm) {
                vals[k] = aa * __ldg(z + (size_t)(v0 + k) * HD + t) + bb;
                bs[k] = __ldg(batch + v0 + k);
            }
        }
        for (int k = 0; k < mm; k++) {
            if (bs[k] != cur) {
                atomicAdd(&g_ssum[cur * HD + t], s);
                atomicMax(&g_smax[cur * HD + t], fenc(m));
                if (t == 0) atomicAdd(&g_cnt[cur], c);
                cur = bs[k]; s = 0.f; m = NEG_INF; c = 0;
            }
            s += vals[k]; m = fmaxf(m, vals[k]); c++;
        }
    }
    atomicAdd(&g_ssum[cur * HD + t], s);
    atomicMax(&g_smax[cur * HD + t], fenc(m));
    if (t == 0) atomicAdd(&g_cnt[cur], c);
}
__global__ void graph_k(int B) {
    int i = blockIdx.x * blockDim.x + threadIdx.x;
    if (i >= B * 384) return;
    int b = i / 384, c = i % 384;
    float o;
    if (c < 128)      o = g_ssum[b * HD + c] / (float)max(g_cnt[b], 1);
    else if (c < 256) o = (g_cnt[b] == 0) ? 0.f : fdec(g_smax[b * HD + c - 128]);
    else              o = g_ssum[b * HD + (c - 256)];
    g_graph[i] = o;
}
__global__ void comb_k(int rows) {
    int i = blockIdx.x * blockDim.x + threadIdx.x;
    int total = rows * 128;
    if (i >= total) return;
    int r = i >> 7, c4 = i & 127;
    float4 v;
    if (c4 < 96) v = *(const float4*)&g_graph[(r >> 5) * 384 + c4 * 4];
    else         v = *(const float4*)&g_oe[(size_t)r * HD + (c4 - 96) * 4];
    ((float4*)g_comb)[i] = v;
}

// ---------------- SIMT GEMM NT=64 ----------------
template <int NT, bool RELU>
__global__ __launch_bounds__(2 * NT, 2)
void gemm_k(const float* __restrict__ A, const float* __restrict__ W,
            const float* __restrict__ bias, float* __restrict__ out, int M, int K) {
    constexpr int THREADS = 2 * NT;
    constexpr int TX = NT / 8;
    __shared__ float As[32][128];
    __shared__ float Bs[32][NT];
    const int tid = threadIdx.x;
    const int tx = tid % TX;
    const int ty = tid / TX;
    const int rowBase = blockIdx.x * 128;
    float acc[8][8];
#pragma unroll
    for (int j = 0; j < 8; j++)
#pragma unroll
        for (int i = 0; i < 8; i++) acc[j][i] = 0.f;
    for (int kt = 0; kt < K; kt += 32) {
#pragma unroll
        for (int q0 = 0; q0 < 1024 / THREADS; q0++) {
            int q = q0 * THREADS + tid;
            int r = q >> 3;
            int kq = (q & 7) * 4;
            float4 v = make_float4(0.f, 0.f, 0.f, 0.f);
            int gr = rowBase + r;
            if (gr < M) v = *(const float4*)(A + (size_t)gr * K + kt + kq);
            As[kq + 0][r] = v.x; As[kq + 1][r] = v.y;
            As[kq + 2][r] = v.z; As[kq + 3][r] = v.w;
        }
#pragma unroll
        for (int q0 = 0; q0 < (32 * NT / 4) / THREADS; q0++) {
            int q = q0 * THREADS + tid;
            int kl = q / (NT / 4);
            int c4 = (q % (NT / 4)) * 4;
            *(float4*)&Bs[kl][c4] = *(const float4*)(W + (size_t)(kt + kl) * NT + c4);
        }
        __syncthreads();
#pragma unroll
        for (int kl = 0; kl < 32; kl++) {
            float a[8], b[8];
            *(float4*)&a[0] = *(const float4*)&As[kl][ty * 8];
            *(float4*)&a[4] = *(const float4*)&As[kl][ty * 8 + 4];
            *(float4*)&b[0] = *(const float4*)&Bs[kl][tx * 8];
            *(float4*)&b[4] = *(const float4*)&Bs[kl][tx * 8 + 4];
#pragma unroll
            for (int j = 0; j < 8; j++)
#pragma unroll
                for (int i = 0; i < 8; i++)
                    acc[j][i] = fmaf(a[j], b[i], acc[j][i]);
        }
        __syncthreads();
    }
    float br[8];
#pragma unroll
    for (int i = 0; i < 8; i++) br[i] = __ldg(bias + tx * 8 + i);
#pragma unroll
    for (int j = 0; j < 8; j++) {
        int gr = rowBase + ty * 8 + j;
        if (gr >= M) continue;
        float v[8];
#pragma unroll
        for (int i = 0; i < 8; i++) {
            v[i] = acc[j][i] + br[i];
            if (RELU) v[i] = fmaxf(v[i], 0.f);
        }
        float* op = out + (size_t)gr * NT + tx * 8;
        *(float4*)op       = make_float4(v[0], v[1], v[2], v[3]);
        *(float4*)(op + 4) = make_float4(v[4], v[5], v[6], v[7]);
    }
}

// ---------------- final dot ----------------
__global__ void s3_k(const float* __restrict__ s2, const float* __restrict__ W,
                     const float* __restrict__ b, float* __restrict__ out, int rows) {
    int warp = (blockIdx.x * blockDim.x + threadIdx.x) >> 5;
    int lane = threadIdx.x & 31;
    if (warp >= rows) return;
    const float* row = s2 + (size_t)warp * 64;
    float s = row[lane] * W[lane] + row[lane + 32] * W[lane + 32];
#pragma unroll
    for (int o = 16; o > 0; o >>= 1) s += __shfl_down_sync(0xffffffffu, s, o);
    if (lane == 0) out[warp] = s + b[0];
}

// ---------------- launch ----------------
extern "C" void kernel_launch(void* const* d_in, const int* in_sizes, int n_in,
                              void* d_out, int out_size) {
    const float* x      = (const float*)d_in[0];
    const int*   ei     = (const int*)d_in[1];
    const float* orders = (const float*)d_in[2];
    const int*   batch  = (const int*)d_in[3];
    const float* gW1    = (const float*)d_in[4];
    const float* gb1    = (const float*)d_in[5];
    const float* gW2    = (const float*)d_in[6];
    const float* gb2    = (const float*)d_in[7];
    const float* gamma  = (const float*)d_in[8];
    const float* beta   = (const float*)d_in[9];
    const float* oW1    = (const float*)d_in[10];
    const float* ob1    = (const float*)d_in[11];
    const float* oW2    = (const float*)d_in[12];
    const float* ob2    = (const float*)d_in[13];
    const float* sW1    = (const float*)d_in[14];
    const float* sb1    = (const float*)d_in[15];
    const float* sW2    = (const float*)d_in[16];
    const float* sb2    = (const float*)d_in[17];
    const float* sW3    = (const float*)d_in[18];
    const float* sb3    = (const float*)d_in[19];
    float* out = (float*)d_out;

    const int n = in_sizes[0] / HD;
    const int E = in_sizes[1] / 2;
    const int B = in_sizes[2] / (OMAX * 32);
    const int L = in_sizes[4] / (HD * HD);
    const int rows = B * OMAX;
    const float invN = 1.0f / (float)n;

    float *zB, *aggB, *z1B, *oeB, *combB, *s1B, *s2B;
    uint4* wfB;
    cudaGetSymbolAddress((void**)&zB, g_z);
    cudaGetSymbolAddress((void**)&aggB, g_agg);
    cudaGetSymbolAddress((void**)&z1B, g_z1);
    cudaGetSymbolAddress((void**)&oeB, g_oe);
    cudaGetSymbolAddress((void**)&combB, g_comb);
    cudaGetSymbolAddress((void**)&s1B, g_s1);
    cudaGetSymbolAddress((void**)&s2B, g_s2);
    cudaGetSymbolAddress((void**)&wfB, g_wfrag);

    prep_k<<<720, 256>>>(gW1, gW2, oW1, oW2, sW1);

    // CSR build
    zero_deg_k<<<(n + 255) / 256, 256>>>(n);
    hist_k<<<(E + 255) / 256, 256>>>(ei, E);
    partial_k<<<256, 256>>>(n);
    scanb_k<<<1, 256>>>();
    rowptr_k<<<256, 256>>>(n, E);
    fill_k<<<(E + 255) / 256, 256>>>(ei, E);

    const int gGrid = (n + 127) / 128;
    for (int l = 0; l < L; l++) {
        const float* src = (l == 0) ? x : zB;
        int pl = (l > 0) ? (l - 1) : 0;
        // layer 0: raw x (no BN, no relu); layers 1+: BN(prev stats) + relu
        gather_k<<<(n + 7) / 8, 256>>>(src, aggB, gamma + pl * HD, beta + pl * HD,
                                       n, l > 0, l > 0, invN);
        gemm_f<<<gGrid, 128>>>(aggB, wfB + (size_t)l * 4096, gb1 + l * HD,
                               z1B, n, HD, 1, 1);
        gemm_f<<<gGrid, 128>>>(z1B, wfB + (size_t)(3 + l) * 4096, gb2 + l * HD,
                               zB, n, HD, 0, 2);
    }

    pool_init_k<<<(B * HD + 255) / 256, 256>>>(B);
    pool_k<<<(n + 255) / 256, 128>>>(zB, batch, gamma + (L - 1) * HD, beta + (L - 1) * HD,
                                     n, invN);
    graph_k<<<(B * 384 + 255) / 256, 256>>>(B);

    const int hGrid = (rows + 127) / 128;
    gemm_f<<<hGrid, 128>>>(orders, wfB + 24576, ob1, z1B, rows, 32, 1, 0);
    gemm_f<<<hGrid, 128>>>(z1B, wfB + 25600, ob2, oeB, rows, HD, 0, 0);
    comb_k<<<(rows * 128 + 255) / 256, 256>>>(rows);
    gemm_f<<<hGrid, 128>>>(combB, wfB + 29696, sb1, s1B, rows, 512, 1, 0);
    gemm_k<64, true><<<(rows + 127) / 128, 128>>>(s1B, sW2, sb2, s2B, rows, HD);
    s3_k<<<(rows + 7) / 8, 256>>>(s2B, sW3, sb3, out, rows);
}

// round 9
// speedup vs baseline: 1.5951x; 1.5951x over previous
#include <cuda_runtime.h>
#include <cuda_bf16.h>
#include <cstdint>

#define NMAX 100000
#define EMAX 1600000
#define HD   128
#define BMAX 256
#define OMAX 32

// ---------------- static scratch ----------------
__device__ float    g_z   [NMAX * HD];     // pre-BN layer output
__device__ float    g_agg [NMAX * HD];
__device__ float    g_z1  [NMAX * HD];
__device__ float    g_stats[2 * HD];
__device__ float    g_ssum[BMAX * HD];
__device__ unsigned g_smax[BMAX * HD];
__device__ int      g_cnt [BMAX];
__device__ float    g_graph[BMAX * 384];
__device__ float    g_oe  [BMAX * OMAX * HD];
__device__ float    g_comb[BMAX * OMAX * 512];
__device__ float    g_s1  [BMAX * OMAX * HD];
__device__ float    g_s2  [BMAX * OMAX * 64];
__device__ uint4    g_wfrag[46080];
// CSR
__device__ int      g_deg   [NMAX];
__device__ int      g_rowptr[NMAX + 1];
__device__ int      g_cursor[NMAX];
__device__ int      g_ssrc  [EMAX];
__device__ int      g_bsum  [256];
__device__ int      g_boff  [256];

#define MMA_BF16(c, a, b0, b1) \
    asm volatile("mma.sync.aligned.m16n8k16.row.col.f32.bf16.bf16.f32 " \
        "{%0,%1,%2,%3}, {%4,%5,%6,%7}, {%8,%9}, {%0,%1,%2,%3};" \
        : "+f"((c)[0]), "+f"((c)[1]), "+f"((c)[2]), "+f"((c)[3]) \
        : "r"((a)[0]), "r"((a)[1]), "r"((a)[2]), "r"((a)[3]), "r"(b0), "r"(b1))

__device__ __forceinline__ void cvt_hilo(float2 v, uint32_t& hi, uint32_t& lo) {
    __nv_bfloat162 h = __float22bfloat162_rn(v);
    float hx = __bfloat162float(h.x), hy = __bfloat162float(h.y);
    __nv_bfloat162 l = __float22bfloat162_rn(make_float2(v.x - hx, v.y - hy));
    hi = *(uint32_t*)&h;
    lo = *(uint32_t*)&l;
}

__device__ __forceinline__ unsigned fenc(float f) {
    unsigned u = __float_as_uint(f);
    return (u & 0x80000000u) ? ~u : (u | 0x80000000u);
}
__device__ __forceinline__ float fdec(unsigned u) {
    unsigned b = (u & 0x80000000u) ? (u & 0x7FFFFFFFu) : ~u;
    return __uint_as_float(b);
}
#define NEG_INF __uint_as_float(0xff800000u)

// ---------------- weight prep (fragment order) ----------------
__global__ void prep_k(const float* __restrict__ gW1, const float* __restrict__ gW2,
                       const float* __restrict__ oW1f, const float* __restrict__ oW2f,
                       const float* __restrict__ sW1f) {
    int idx = blockIdx.x * blockDim.x + threadIdx.x;
    if (idx >= 184320) return;
    const float* W; int el;
    if (idx < 98304) {
        int m = idx / 16384; el = idx % 16384;
        W = (m < 3) ? gW1 + (size_t)m * 16384 : gW2 + (size_t)(m - 3) * 16384;
    } else if (idx < 102400) { el = idx - 98304;  W = oW1f; }
    else if   (idx < 118784) { el = idx - 102400; W = oW2f; }
    else                     { el = idx - 118784; W = sW1f; }
    int ks = el >> 11;
    int rem = el & 2047;
    int ntile = rem >> 7;
    int lane = (rem & 127) >> 2;
    int q = rem & 3;
    int n = ntile * 8 + (lane >> 2);
    int k = ks * 16 + (lane & 3) * 2 + ((q & 1) ? 8 : 0);
    float v0 = W[(size_t)k * 128 + n];
    float v1 = W[(size_t)(k + 1) * 128 + n];
    uint32_t r;
    __nv_bfloat16 h0 = __float2bfloat16(v0), h1 = __float2bfloat16(v1);
    if (q < 2) {
        r = ((uint32_t)__bfloat16_as_ushort(h1) << 16) | __bfloat16_as_ushort(h0);
    } else {
        __nv_bfloat16 l0 = __float2bfloat16(v0 - __bfloat162float(h0));
        __nv_bfloat16 l1 = __float2bfloat16(v1 - __bfloat162float(h1));
        r = ((uint32_t)__bfloat16_as_ushort(l1) << 16) | __bfloat16_as_ushort(l0);
    }
    ((uint32_t*)g_wfrag)[idx] = r;
}

// ---------------- CSR build ----------------
__global__ void zero_deg_k(int n) {
    int i = blockIdx.x * blockDim.x + threadIdx.x;
    if (i < n) g_deg[i] = 0;
}
__global__ void hist_k(const int* __restrict__ ei, int E) {
    int i = blockIdx.x * blockDim.x + threadIdx.x;
    if (i < E) atomicAdd(&g_deg[__ldg(ei + E + i)], 1);
}
__global__ void partial_k(int n) {
    __shared__ int sd[256];
    int C = (n + 255) / 256;
    int start = blockIdx.x * C, end = min(start + C, n);
    int s = 0;
    for (int i = start + threadIdx.x; i < end; i += 256) s += g_deg[i];
    sd[threadIdx.x] = s;
    __syncthreads();
    for (int o = 128; o > 0; o >>= 1) {
        if (threadIdx.x < o) sd[threadIdx.x] += sd[threadIdx.x + o];
        __syncthreads();
    }
    if (threadIdx.x == 0) g_bsum[blockIdx.x] = sd[0];
}
__global__ void scanb_k() {
    __shared__ int sd[256];
    int t = threadIdx.x;
    sd[t] = g_bsum[t];
    __syncthreads();
    for (int o = 1; o < 256; o <<= 1) {
        int v = (t >= o) ? sd[t - o] : 0;
        __syncthreads();
        sd[t] += v;
        __syncthreads();
    }
    g_boff[t] = sd[t] - g_bsum[t];
}
__global__ void rowptr_k(int n, int E) {
    __shared__ int sd[256];
    int C = (n + 255) / 256;
    int start = blockIdx.x * C, end = min(start + C, n);
    int off = g_boff[blockIdx.x];
    for (int base = start; base < end; base += 256) {
        int i = base + threadIdx.x;
        int d = (i < end) ? g_deg[i] : 0;
        sd[threadIdx.x] = d;
        __syncthreads();
        for (int o = 1; o < 256; o <<= 1) {
            int v = (threadIdx.x >= o) ? sd[threadIdx.x - o] : 0;
            __syncthreads();
            sd[threadIdx.x] += v;
            __syncthreads();
        }
        if (i < end) {
            int ex = off + sd[threadIdx.x] - d;
            g_rowptr[i] = ex;
            g_cursor[i] = ex;
        }
        int tot = sd[255];
        __syncthreads();
        off += tot;
    }
    if (blockIdx.x == 255 && threadIdx.x == 0) g_rowptr[n] = E;
}
__global__ void fill_k(const int* __restrict__ ei, int E) {
    int i = blockIdx.x * blockDim.x + threadIdx.x;
    if (i >= E) return;
    int s = __ldg(ei + i);
    int d = __ldg(ei + E + i);
    int pos = atomicAdd(&g_cursor[d], 1);
    g_ssrc[pos] = s;
}

// ---------------- gather with fused BN(+relu): agg[d] = Σ f(z[src]) + f(z[d]) ----------------
// Layer 0: useBn=0, doRelu=0 -> pure aggregation of raw x.
__global__ void gather_k(const float* __restrict__ z, float* __restrict__ agg,
                         const float* __restrict__ gamma, const float* __restrict__ beta,
                         int n, int useBn, int doRelu, float invN) {
    __shared__ float sa[128], sb[128];
    if (threadIdx.x < 128) {
        if (useBn) {
            float mu = g_stats[threadIdx.x] * invN;
            float q = g_stats[128 + threadIdx.x] * invN;
            float var = q - mu * mu;
            float aa = gamma[threadIdx.x] * rsqrtf(var + 1e-5f);
            sa[threadIdx.x] = aa;
            sb[threadIdx.x] = beta[threadIdx.x] - mu * aa;
        } else {
            sa[threadIdx.x] = 1.f;
            sb[threadIdx.x] = 0.f;
        }
    }
    __syncthreads();
    int wid = blockIdx.x * (blockDim.x >> 5) + (threadIdx.x >> 5);
    int lane = threadIdx.x & 31;
    if (wid >= n) return;
    float4 a4 = *(float4*)&sa[lane * 4];
    float4 b4 = *(float4*)&sb[lane * 4];

    auto xf = [&](float4 v) {
        float4 r;
        r.x = a4.x * v.x + b4.x; r.y = a4.y * v.y + b4.y;
        r.z = a4.z * v.z + b4.z; r.w = a4.w * v.w + b4.w;
        if (doRelu) {
            r.x = fmaxf(r.x, 0.f); r.y = fmaxf(r.y, 0.f);
            r.z = fmaxf(r.z, 0.f); r.w = fmaxf(r.w, 0.f);
        }
        return r;
    };

    int beg = __ldg(&g_rowptr[wid]);
    int end = __ldg(&g_rowptr[wid + 1]);
    const float4* z4 = (const float4*)z;
    float4 acc = xf(__ldg(z4 + (size_t)wid * 32 + lane));
    int j = beg;
    for (; j + 4 <= end; j += 4) {
        int s0 = __ldg(&g_ssrc[j]);
        int s1 = __ldg(&g_ssrc[j + 1]);
        int s2 = __ldg(&g_ssrc[j + 2]);
        int s3 = __ldg(&g_ssrc[j + 3]);
        float4 v0 = xf(__ldg(z4 + (size_t)s0 * 32 + lane));
        float4 v1 = xf(__ldg(z4 + (size_t)s1 * 32 + lane));
        float4 v2 = xf(__ldg(z4 + (size_t)s2 * 32 + lane));
        float4 v3 = xf(__ldg(z4 + (size_t)s3 * 32 + lane));
        acc.x += v0.x + v1.x + v2.x + v3.x;
        acc.y += v0.y + v1.y + v2.y + v3.y;
        acc.z += v0.z + v1.z + v2.z + v3.z;
        acc.w += v0.w + v1.w + v2.w + v3.w;
    }
    for (; j < end; j++) {
        int s = __ldg(&g_ssrc[j]);
        float4 v = xf(__ldg(z4 + (size_t)s * 32 + lane));
        acc.x += v.x; acc.y += v.y; acc.z += v.z; acc.w += v.w;
    }
    ((float4*)agg)[(size_t)wid * 32 + lane] = acc;
}

// ---------------- mma GEMM: 64 rows/block (R4-proven shape), fused stats option ----------
// statsMode: 0 = none, 1 = zero g_stats (block 0), 2 = accumulate column sums/sumsq
__global__ void __launch_bounds__(128) gemm_f(
    const float* __restrict__ A, const uint4* __restrict__ wf,
    const float* __restrict__ bias, float* __restrict__ out,
    int M, int K, int relu, int statsMode) {
    __shared__ float sred[256];
    const int tid = threadIdx.x;
    const int lane = tid & 31;
    const int warp = tid >> 5;
    const int fr = lane >> 2;
    const int c2 = (lane & 3) * 2;
    const int rowBase = blockIdx.x * 64 + warp * 16;
    const int r0 = rowBase + fr;
    const int r1 = r0 + 8;
    const bool v0 = r0 < M, v1 = r1 < M;

    if (statsMode == 1 && blockIdx.x == 0 && tid < 128) {
        g_stats[tid] = 0.f;
        g_stats[tid + 128] = 0.f;
    }

    float acc[16][4];
#pragma unroll
    for (int t = 0; t < 16; t++)
#pragma unroll
        for (int i = 0; i < 4; i++) acc[t][i] = 0.f;

    const uint4* wp = wf + lane;
    const int nks = K >> 4;
    const float2 z2 = make_float2(0.f, 0.f);
    for (int ks = 0; ks < nks; ks++) {
        const float* a0p = A + (size_t)r0 * K + ks * 16 + c2;
        const float* a1p = A + (size_t)r1 * K + ks * 16 + c2;
        float2 x00 = v0 ? __ldg((const float2*)a0p)       : z2;
        float2 x10 = v1 ? __ldg((const float2*)a1p)       : z2;
        float2 x02 = v0 ? __ldg((const float2*)(a0p + 8)) : z2;
        float2 x12 = v1 ? __ldg((const float2*)(a1p + 8)) : z2;
        uint32_t ah[4], al[4];
        cvt_hilo(x00, ah[0], al[0]);
        cvt_hilo(x10, ah[1], al[1]);
        cvt_hilo(x02, ah[2], al[2]);
        cvt_hilo(x12, ah[3], al[3]);
        const uint4* wk = wp + ks * 512;
#pragma unroll
        for (int nt = 0; nt < 16; nt++) {
            uint4 w = __ldg(wk + nt * 32);
            MMA_BF16(acc[nt], ah, w.x, w.y);   // ahi * bhi
            MMA_BF16(acc[nt], ah, w.z, w.w);   // ahi * blo
            MMA_BF16(acc[nt], al, w.x, w.y);   // alo * bhi
        }
    }

    if (statsMode == 2) {
        sred[tid] = 0.f;
        sred[tid + 128] = 0.f;
        __syncthreads();
    }

    float* o0 = out + (size_t)r0 * 128;
    float* o1 = out + (size_t)r1 * 128;
#pragma unroll
    for (int nt = 0; nt < 16; nt++) {
        int c = nt * 8 + c2;
        float bx = __ldg(bias + c), by = __ldg(bias + c + 1);
        float2 w0 = make_float2(acc[nt][0] + bx, acc[nt][1] + by);
        float2 w1 = make_float2(acc[nt][2] + bx, acc[nt][3] + by);
        if (relu) {
            w0.x = fmaxf(w0.x, 0.f); w0.y = fmaxf(w0.y, 0.f);
            w1.x = fmaxf(w1.x, 0.f); w1.y = fmaxf(w1.y, 0.f);
        }
        if (v0) *(float2*)(o0 + c) = w0;
        if (v1) *(float2*)(o1 + c) = w1;
        if (statsMode == 2) {
            float s0 = 0.f, s1 = 0.f, q0 = 0.f, q1 = 0.f;
            if (v0) { s0 += w0.x; s1 += w0.y; q0 += w0.x * w0.x; q1 += w0.y * w0.y; }
            if (v1) { s0 += w1.x; s1 += w1.y; q0 += w1.x * w1.x; q1 += w1.y * w1.y; }
#pragma unroll
            for (int o = 4; o < 32; o <<= 1) {
                s0 += __shfl_xor_sync(0xffffffffu, s0, o);
                s1 += __shfl_xor_sync(0xffffffffu, s1, o);
                q0 += __shfl_xor_sync(0xffffffffu, q0, o);
                q1 += __shfl_xor_sync(0xffffffffu, q1, o);
            }
            if (lane < 4) {
                atomicAdd(&sred[c], s0);
                atomicAdd(&sred[c + 1], s1);
                atomicAdd(&sred[128 + c], q0);
                atomicAdd(&sred[128 + c + 1], q1);
            }
        }
    }
    if (statsMode == 2) {
        __syncthreads();
        atomicAdd(&g_stats[tid], sred[tid]);
        atomicAdd(&g_stats[tid + 128], sred[tid + 128]);
    }
}

// ---------------- pooling with fused BN (no relu on last layer) ----------------
__global__ void pool_init_k(int B) {
    int i = blockIdx.x * blockDim.x + threadIdx.x;
    if (i < B * HD) { g_ssum[i] = 0.f; g_smax[i] = 0x007FFFFFu; }
    if (i < B) g_cnt[i] = 0;
}
__global__ void pool_k(const float* __restrict__ z, const int* __restrict__ batch,
                       const float* __restrict__ gamma, const float* __restrict__ beta,
                       int n, float invN) {
    const int t = threadIdx.x;                // 128 threads, one per feature
    float mu = g_stats[t] * invN;
    float q = g_stats[128 + t] * invN;
    float var = q - mu * mu;
    float aa = gamma[t] * rsqrtf(var + 1e-5f);
    float bb = beta[t] - mu * aa;

    int start = blockIdx.x * 256;
    int end = min(start + 256, n);
    if (start >= end) return;
    int cur = __ldg(batch + start);
    float s = 0.f, m = NEG_INF;
    int c = 0;
    for (int v0 = start; v0 < end; v0 += 8) {
        float vals[8]; int bs[8];
        int mm = min(8, end - v0);
#pragma unroll
        for (int k = 0; k < 8; k++) {
            if (k < mm) {
                vals[k] = aa * __ldg(z + (size_t)(v0 + k) * HD + t) + bb;
                bs[k] = __ldg(batch + v0 + k);
            }
        }
        for (int k = 0; k < mm; k++) {
            if (bs[k] != cur) {
                atomicAdd(&g_ssum[cur * HD + t], s);
                atomicMax(&g_smax[cur * HD + t], fenc(m));
                if (t == 0) atomicAdd(&g_cnt[cur], c);
                cur = bs[k]; s = 0.f; m = NEG_INF; c = 0;
            }
            s += vals[k]; m = fmaxf(m, vals[k]); c++;
        }
    }
    atomicAdd(&g_ssum[cur * HD + t], s);
    atomicMax(&g_smax[cur * HD + t], fenc(m));
    if (t == 0) atomicAdd(&g_cnt[cur], c);
}
__global__ void graph_k(int B) {
    int i = blockIdx.x * blockDim.x + threadIdx.x;
    if (i >= B * 384) return;
    int b = i / 384, c = i % 384;
    float o;
    if (c < 128)      o = g_ssum[b * HD + c] / (float)max(g_cnt[b], 1);
    else if (c < 256) o = (g_cnt[b] == 0) ? 0.f : fdec(g_smax[b * HD + c - 128]);
    else              o = g_ssum[b * HD + (c - 256)];
    g_graph[i] = o;
}
__global__ void comb_k(int rows) {
    int i = blockIdx.x * blockDim.x + threadIdx.x;
    int total = rows * 128;
    if (i >= total) return;
    int r = i >> 7, c4 = i & 127;
    float4 v;
    if (c4 < 96) v = *(const float4*)&g_graph[(r >> 5) * 384 + c4 * 4];
    else         v = *(const float4*)&g_oe[(size_t)r * HD + (c4 - 96) * 4];
    ((float4*)g_comb)[i] = v;
}

// ---------------- SIMT GEMM NT=64 ----------------
template <int NT, bool RELU>
__global__ __launch_bounds__(2 * NT, 2)
void gemm_k(const float* __restrict__ A, const float* __restrict__ W,
            const float* __restrict__ bias, float* __restrict__ out, int M, int K) {
    constexpr int THREADS = 2 * NT;
    constexpr int TX = NT / 8;
    __shared__ float As[32][128];
    __shared__ float Bs[32][NT];
    const int tid = threadIdx.x;
    const int tx = tid % TX;
    const int ty = tid / TX;
    const int rowBase = blockIdx.x * 128;
    float acc[8][8];
#pragma unroll
    for (int j = 0; j < 8; j++)
#pragma unroll
        for (int i = 0; i < 8; i++) acc[j][i] = 0.f;
    for (int kt = 0; kt < K; kt += 32) {
#pragma unroll
        for (int q0 = 0; q0 < 1024 / THREADS; q0++) {
            int q = q0 * THREADS + tid;
            int r = q >> 3;
            int kq = (q & 7) * 4;
            float4 v = make_float4(0.f, 0.f, 0.f, 0.f);
            int gr = rowBase + r;
            if (gr < M) v = *(const float4*)(A + (size_t)gr * K + kt + kq);
            As[kq + 0][r] = v.x; As[kq + 1][r] = v.y;
            As[kq + 2][r] = v.z; As[kq + 3][r] = v.w;
        }
#pragma unroll
        for (int q0 = 0; q0 < (32 * NT / 4) / THREADS; q0++) {
            int q = q0 * THREADS + tid;
            int kl = q / (NT / 4);
            int c4 = (q % (NT / 4)) * 4;
            *(float4*)&Bs[kl][c4] = *(const float4*)(W + (size_t)(kt + kl) * NT + c4);
        }
        __syncthreads();
#pragma unroll
        for (int kl = 0; kl < 32; kl++) {
            float a[8], b[8];
            *(float4*)&a[0] = *(const float4*)&As[kl][ty * 8];
            *(float4*)&a[4] = *(const float4*)&As[kl][ty * 8 + 4];
            *(float4*)&b[0] = *(const float4*)&Bs[kl][tx * 8];
            *(float4*)&b[4] = *(const float4*)&Bs[kl][tx * 8 + 4];
#pragma unroll
            for (int j = 0; j < 8; j++)
#pragma unroll
                for (int i = 0; i < 8; i++)
                    acc[j][i] = fmaf(a[j], b[i], acc[j][i]);
        }
        __syncthreads();
    }
    float br[8];
#pragma unroll
    for (int i = 0; i < 8; i++) br[i] = __ldg(bias + tx * 8 + i);
#pragma unroll
    for (int j = 0; j < 8; j++) {
        int gr = rowBase + ty * 8 + j;
        if (gr >= M) continue;
        float v[8];
#pragma unroll
        for (int i = 0; i < 8; i++) {
            v[i] = acc[j][i] + br[i];
            if (RELU) v[i] = fmaxf(v[i], 0.f);
        }
        float* op = out + (size_t)gr * NT + tx * 8;
        *(float4*)op       = make_float4(v[0], v[1], v[2], v[3]);
        *(float4*)(op + 4) = make_float4(v[4], v[5], v[6], v[7]);
    }
}

// ---------------- final dot ----------------
__global__ void s3_k(const float* __restrict__ s2, const float* __restrict__ W,
                     const float* __restrict__ b, float* __restrict__ out, int rows) {
    int warp = (blockIdx.x * blockDim.x + threadIdx.x) >> 5;
    int lane = threadIdx.x & 31;
    if (warp >= rows) return;
    const float* row = s2 + (size_t)warp * 64;
    float s = row[lane] * W[lane] + row[lane + 32] * W[lane + 32];
#pragma unroll
    for (int o = 16; o > 0; o >>= 1) s += __shfl_down_sync(0xffffffffu, s, o);
    if (lane == 0) out[warp] = s + b[0];
}

// ---------------- launch ----------------
extern "C" void kernel_launch(void* const* d_in, const int* in_sizes, int n_in,
                              void* d_out, int out_size) {
    const float* x      = (const float*)d_in[0];
    const int*   ei     = (const int*)d_in[1];
    const float* orders = (const float*)d_in[2];
    const int*   batch  = (const int*)d_in[3];
    const float* gW1    = (const float*)d_in[4];
    const float* gb1    = (const float*)d_in[5];
    const float* gW2    = (const float*)d_in[6];
    const float* gb2    = (const float*)d_in[7];
    const float* gamma  = (const float*)d_in[8];
    const float* beta   = (const float*)d_in[9];
    const float* oW1    = (const float*)d_in[10];
    const float* ob1    = (const float*)d_in[11];
    const float* oW2    = (const float*)d_in[12];
    const float* ob2    = (const float*)d_in[13];
    const float* sW1    = (const float*)d_in[14];
    const float* sb1    = (const float*)d_in[15];
    const float* sW2    = (const float*)d_in[16];
    const float* sb2    = (const float*)d_in[17];
    const float* sW3    = (const float*)d_in[18];
    const float* sb3    = (const float*)d_in[19];
    float* out = (float*)d_out;

    const int n = in_sizes[0] / HD;
    const int E = in_sizes[1] / 2;
    const int B = in_sizes[2] / (OMAX * 32);
    const int L = in_sizes[4] / (HD * HD);
    const int rows = B * OMAX;
    const float invN = 1.0f / (float)n;

    float *zB, *aggB, *z1B, *oeB, *combB, *s1B, *s2B;
    uint4* wfB;
    cudaGetSymbolAddress((void**)&zB, g_z);
    cudaGetSymbolAddress((void**)&aggB, g_agg);
    cudaGetSymbolAddress((void**)&z1B, g_z1);
    cudaGetSymbolAddress((void**)&oeB, g_oe);
    cudaGetSymbolAddress((void**)&combB, g_comb);
    cudaGetSymbolAddress((void**)&s1B, g_s1);
    cudaGetSymbolAddress((void**)&s2B, g_s2);
    cudaGetSymbolAddress((void**)&wfB, g_wfrag);

    prep_k<<<720, 256>>>(gW1, gW2, oW1, oW2, sW1);

    // CSR build
    zero_deg_k<<<(n + 255) / 256, 256>>>(n);
    hist_k<<<(E + 255) / 256, 256>>>(ei, E);
    partial_k<<<256, 256>>>(n);
    scanb_k<<<1, 256>>>();
    rowptr_k<<<256, 256>>>(n, E);
    fill_k<<<(E + 255) / 256, 256>>>(ei, E);

    const int gGrid = (n + 63) / 64;
    for (int l = 0; l < L; l++) {
        const float* src = (l == 0) ? x : zB;
        int pl = (l > 0) ? (l - 1) : 0;
        // layer 0: raw x (no BN, no relu); layers 1+: BN(prev stats) + relu
        gather_k<<<(n + 7) / 8, 256>>>(src, aggB, gamma + pl * HD, beta + pl * HD,
                                       n, l > 0, l > 0, invN);
        gemm_f<<<gGrid, 128>>>(aggB, wfB + (size_t)l * 4096, gb1 + l * HD,
                               z1B, n, HD, 1, 1);
        gemm_f<<<gGrid, 128>>>(z1B, wfB + (size_t)(3 + l) * 4096, gb2 + l * HD,
                               zB, n, HD, 0, 2);
    }

    pool_init_k<<<(B * HD + 255) / 256, 256>>>(B);
    pool_k<<<(n + 255) / 256, 128>>>(zB, batch, gamma + (L - 1) * HD, beta + (L - 1) * HD,
                                     n, invN);
    graph_k<<<(B * 384 + 255) / 256, 256>>>(B);

    const int hGrid = (rows + 63) / 64;
    gemm_f<<<hGrid, 128>>>(orders, wfB + 24576, ob1, z1B, rows, 32, 1, 0);
    gemm_f<<<hGrid, 128>>>(z1B, wfB + 25600, ob2, oeB, rows, HD, 0, 0);
    comb_k<<<(rows * 128 + 255) / 256, 256>>>(rows);
    gemm_f<<<hGrid, 128>>>(combB, wfB + 29696, sb1, s1B, rows, 512, 1, 0);
    gemm_k<64, true><<<(rows + 127) / 128, 128>>>(s1B, sW2, sb2, s2B, rows, HD);
    s3_k<<<(rows + 7) / 8, 256>>>(s2B, sW3, sb3, out, rows);
}

// round 10
// speedup vs baseline: 1.7455x; 1.0942x over previous
#include <cuda_runtime.h>
#include <cuda_bf16.h>
#include <cstdint>

#define NMAX 100000
#define EMAX 1600000
#define HD   128
#define BMAX 256
#define OMAX 32

// ---------------- static scratch ----------------
__device__ float    g_z   [NMAX * HD];     // pre-BN layer output
__device__ float    g_agg [NMAX * HD];
__device__ float    g_z1  [NMAX * HD];
__device__ float    g_stats[512];          // ping-pong: buf b at offset b*256
__device__ float    g_ssum[BMAX * HD];
__device__ unsigned g_smax[BMAX * HD];
__device__ int      g_cnt [BMAX];
__device__ float    g_graph[BMAX * 384];
__device__ float    g_oe  [BMAX * OMAX * HD];
__device__ float    g_s1  [BMAX * OMAX * HD];
__device__ float    g_s2  [BMAX * OMAX * 64];
__device__ uint4    g_wfrag[46080];
// CSR
__device__ int      g_deg   [NMAX];
__device__ int      g_rowptr[NMAX + 1];
__device__ int      g_cursor[NMAX];
__device__ int      g_ssrc  [EMAX];
__device__ int      g_bsum  [256];
__device__ int      g_boff  [256];

#define MMA_BF16(c, a, b0, b1) \
    asm volatile("mma.sync.aligned.m16n8k16.row.col.f32.bf16.bf16.f32 " \
        "{%0,%1,%2,%3}, {%4,%5,%6,%7}, {%8,%9}, {%0,%1,%2,%3};" \
        : "+f"((c)[0]), "+f"((c)[1]), "+f"((c)[2]), "+f"((c)[3]) \
        : "r"((a)[0]), "r"((a)[1]), "r"((a)[2]), "r"((a)[3]), "r"(b0), "r"(b1))

__device__ __forceinline__ void cvt_hilo(float2 v, uint32_t& hi, uint32_t& lo) {
    __nv_bfloat162 h = __float22bfloat162_rn(v);
    float hx = __bfloat162float(h.x), hy = __bfloat162float(h.y);
    __nv_bfloat162 l = __float22bfloat162_rn(make_float2(v.x - hx, v.y - hy));
    hi = *(uint32_t*)&h;
    lo = *(uint32_t*)&l;
}

__device__ __forceinline__ unsigned fenc(float f) {
    unsigned u = __float_as_uint(f);
    return (u & 0x80000000u) ? ~u : (u | 0x80000000u);
}
__device__ __forceinline__ float fdec(unsigned u) {
    unsigned b = (u & 0x80000000u) ? (u & 0x7FFFFFFFu) : ~u;
    return __uint_as_float(b);
}
#define NEG_INF __uint_as_float(0xff800000u)

// ---------------- weight prep (fragment order) ----------------
__global__ void prep_k(const float* __restrict__ gW1, const float* __restrict__ gW2,
                       const float* __restrict__ oW1f, const float* __restrict__ oW2f,
                       const float* __restrict__ sW1f) {
    int idx = blockIdx.x * blockDim.x + threadIdx.x;
    if (idx >= 184320) return;
    const float* W; int el;
    if (idx < 98304) {
        int m = idx / 16384; el = idx % 16384;
        W = (m < 3) ? gW1 + (size_t)m * 16384 : gW2 + (size_t)(m - 3) * 16384;
    } else if (idx < 102400) { el = idx - 98304;  W = oW1f; }
    else if   (idx < 118784) { el = idx - 102400; W = oW2f; }
    else                     { el = idx - 118784; W = sW1f; }
    int ks = el >> 11;
    int rem = el & 2047;
    int ntile = rem >> 7;
    int lane = (rem & 127) >> 2;
    int q = rem & 3;
    int n = ntile * 8 + (lane >> 2);
    int k = ks * 16 + (lane & 3) * 2 + ((q & 1) ? 8 : 0);
    float v0 = W[(size_t)k * 128 + n];
    float v1 = W[(size_t)(k + 1) * 128 + n];
    uint32_t r;
    __nv_bfloat16 h0 = __float2bfloat16(v0), h1 = __float2bfloat16(v1);
    if (q < 2) {
        r = ((uint32_t)__bfloat16_as_ushort(h1) << 16) | __bfloat16_as_ushort(h0);
    } else {
        __nv_bfloat16 l0 = __float2bfloat16(v0 - __bfloat162float(h0));
        __nv_bfloat16 l1 = __float2bfloat16(v1 - __bfloat162float(h1));
        r = ((uint32_t)__bfloat16_as_ushort(l1) << 16) | __bfloat16_as_ushort(l0);
    }
    ((uint32_t*)g_wfrag)[idx] = r;
}

// ---------------- CSR build ----------------
__global__ void zero_deg_k(int n) {
    int i = blockIdx.x * blockDim.x + threadIdx.x;
    if (i < n) g_deg[i] = 0;
}
__global__ void hist_k(const int* __restrict__ ei, int E) {
    int i = blockIdx.x * blockDim.x + threadIdx.x;
    if (i < E) atomicAdd(&g_deg[__ldg(ei + E + i)], 1);
}
__global__ void partial_k(int n) {
    __shared__ int sd[256];
    int C = (n + 255) / 256;
    int start = blockIdx.x * C, end = min(start + C, n);
    int s = 0;
    for (int i = start + threadIdx.x; i < end; i += 256) s += g_deg[i];
    sd[threadIdx.x] = s;
    __syncthreads();
    for (int o = 128; o > 0; o >>= 1) {
        if (threadIdx.x < o) sd[threadIdx.x] += sd[threadIdx.x + o];
        __syncthreads();
    }
    if (threadIdx.x == 0) g_bsum[blockIdx.x] = sd[0];
}
__global__ void scanb_k() {
    __shared__ int sd[256];
    int t = threadIdx.x;
    sd[t] = g_bsum[t];
    __syncthreads();
    for (int o = 1; o < 256; o <<= 1) {
        int v = (t >= o) ? sd[t - o] : 0;
        __syncthreads();
        sd[t] += v;
        __syncthreads();
    }
    g_boff[t] = sd[t] - g_bsum[t];
}
__global__ void rowptr_k(int n, int E) {
    __shared__ int sd[256];
    int C = (n + 255) / 256;
    int start = blockIdx.x * C, end = min(start + C, n);
    int off = g_boff[blockIdx.x];
    for (int base = start; base < end; base += 256) {
        int i = base + threadIdx.x;
        int d = (i < end) ? g_deg[i] : 0;
        sd[threadIdx.x] = d;
        __syncthreads();
        for (int o = 1; o < 256; o <<= 1) {
            int v = (threadIdx.x >= o) ? sd[threadIdx.x - o] : 0;
            __syncthreads();
            sd[threadIdx.x] += v;
            __syncthreads();
        }
        if (i < end) {
            int ex = off + sd[threadIdx.x] - d;
            g_rowptr[i] = ex;
            g_cursor[i] = ex;
        }
        int tot = sd[255];
        __syncthreads();
        off += tot;
    }
    if (blockIdx.x == 255 && threadIdx.x == 0) g_rowptr[n] = E;
}
__global__ void fill_k(const int* __restrict__ ei, int E) {
    int i = blockIdx.x * blockDim.x + threadIdx.x;
    if (i >= E) return;
    int s = __ldg(ei + i);
    int d = __ldg(ei + E + i);
    int pos = atomicAdd(&g_cursor[d], 1);
    g_ssrc[pos] = s;
}

// ---------------- gather with fused BN(+relu): agg[d] = Σ f(z[src]) + f(z[d]) ----------------
// stR: stats buffer to read (prev layer); stZ: stats buffer block0 zeroes for THIS layer.
// Readers use stR != stZ, so zeroing is race-free.
__global__ void gather_k(const float* __restrict__ z, float* __restrict__ agg,
                         const float* __restrict__ gamma, const float* __restrict__ beta,
                         const float* __restrict__ stR, float* __restrict__ stZ,
                         int n, int useBn, int doRelu, float invN) {
    __shared__ float sa[128], sb[128];
    if (blockIdx.x == 0 && threadIdx.x < 256) stZ[threadIdx.x] = 0.f;
    if (threadIdx.x < 128) {
        if (useBn) {
            float mu = stR[threadIdx.x] * invN;
            float q = stR[128 + threadIdx.x] * invN;
            float var = q - mu * mu;
            float aa = gamma[threadIdx.x] * rsqrtf(var + 1e-5f);
            sa[threadIdx.x] = aa;
            sb[threadIdx.x] = beta[threadIdx.x] - mu * aa;
        } else {
            sa[threadIdx.x] = 1.f;
            sb[threadIdx.x] = 0.f;
        }
    }
    __syncthreads();
    int wid = blockIdx.x * (blockDim.x >> 5) + (threadIdx.x >> 5);
    int lane = threadIdx.x & 31;
    if (wid >= n) return;
    float4 a4 = *(float4*)&sa[lane * 4];
    float4 b4 = *(float4*)&sb[lane * 4];

    auto xf = [&](float4 v) {
        float4 r;
        r.x = a4.x * v.x + b4.x; r.y = a4.y * v.y + b4.y;
        r.z = a4.z * v.z + b4.z; r.w = a4.w * v.w + b4.w;
        if (doRelu) {
            r.x = fmaxf(r.x, 0.f); r.y = fmaxf(r.y, 0.f);
            r.z = fmaxf(r.z, 0.f); r.w = fmaxf(r.w, 0.f);
        }
        return r;
    };

    int beg = __ldg(&g_rowptr[wid]);
    int end = __ldg(&g_rowptr[wid + 1]);
    const float4* z4 = (const float4*)z;
    float4 acc = xf(__ldg(z4 + (size_t)wid * 32 + lane));
    int j = beg;
    for (; j + 4 <= end; j += 4) {
        int s0 = __ldg(&g_ssrc[j]);
        int s1 = __ldg(&g_ssrc[j + 1]);
        int s2 = __ldg(&g_ssrc[j + 2]);
        int s3 = __ldg(&g_ssrc[j + 3]);
        float4 v0 = xf(__ldg(z4 + (size_t)s0 * 32 + lane));
        float4 v1 = xf(__ldg(z4 + (size_t)s1 * 32 + lane));
        float4 v2 = xf(__ldg(z4 + (size_t)s2 * 32 + lane));
        float4 v3 = xf(__ldg(z4 + (size_t)s3 * 32 + lane));
        acc.x += v0.x + v1.x + v2.x + v3.x;
        acc.y += v0.y + v1.y + v2.y + v3.y;
        acc.z += v0.z + v1.z + v2.z + v3.z;
        acc.w += v0.w + v1.w + v2.w + v3.w;
    }
    for (; j < end; j++) {
        int s = __ldg(&g_ssrc[j]);
        float4 v = xf(__ldg(z4 + (size_t)s * 32 + lane));
        acc.x += v.x; acc.y += v.y; acc.z += v.z; acc.w += v.w;
    }
    ((float4*)agg)[(size_t)wid * 32 + lane] = acc;
}

// ---------------- mma GEMM: exact R4-proven shape (64 rows/block, no smem, no barriers) ----
__global__ void __launch_bounds__(128) gemm_f(
    const float* __restrict__ A, const uint4* __restrict__ wf,
    const float* __restrict__ bias, float* __restrict__ out,
    int M, int K, int relu) {
    const int lane = threadIdx.x & 31;
    const int warp = threadIdx.x >> 5;
    const int fr = lane >> 2;
    const int c2 = (lane & 3) * 2;
    const int rowBase = blockIdx.x * 64 + warp * 16;
    const int r0 = rowBase + fr;
    const int r1 = r0 + 8;
    const bool v0 = r0 < M, v1 = r1 < M;
    const uint4* wp = wf + lane;

    float acc[16][4];
#pragma unroll
    for (int t = 0; t < 16; t++)
#pragma unroll
        for (int i = 0; i < 4; i++) acc[t][i] = 0.f;

    const int nks = K >> 4;
    const float2 z = make_float2(0.f, 0.f);
    for (int ks = 0; ks < nks; ks++) {
        const float* a0p = A + (size_t)r0 * K + ks * 16 + c2;
        const float* a1p = A + (size_t)r1 * K + ks * 16 + c2;
        float2 x00 = v0 ? __ldg((const float2*)a0p)       : z;
        float2 x10 = v1 ? __ldg((const float2*)a1p)       : z;
        float2 x02 = v0 ? __ldg((const float2*)(a0p + 8)) : z;
        float2 x12 = v1 ? __ldg((const float2*)(a1p + 8)) : z;
        uint32_t ah[4], al[4];
        cvt_hilo(x00, ah[0], al[0]);
        cvt_hilo(x10, ah[1], al[1]);
        cvt_hilo(x02, ah[2], al[2]);
        cvt_hilo(x12, ah[3], al[3]);
        const uint4* wk = wp + ks * 512;
#pragma unroll
        for (int nt = 0; nt < 16; nt++) {
            uint4 w = __ldg(wk + nt * 32);
            MMA_BF16(acc[nt], ah, w.x, w.y);   // ahi * bhi
            MMA_BF16(acc[nt], ah, w.z, w.w);   // ahi * blo
            MMA_BF16(acc[nt], al, w.x, w.y);   // alo * bhi
        }
    }

    float* o0 = out + (size_t)r0 * 128;
    float* o1 = out + (size_t)r1 * 128;
#pragma unroll
    for (int nt = 0; nt < 16; nt++) {
        int c = nt * 8 + c2;
        float bx = __ldg(bias + c), by = __ldg(bias + c + 1);
        float2 w0 = make_float2(acc[nt][0] + bx, acc[nt][1] + by);
        float2 w1 = make_float2(acc[nt][2] + bx, acc[nt][3] + by);
        if (relu) {
            w0.x = fmaxf(w0.x, 0.f); w0.y = fmaxf(w0.y, 0.f);
            w1.x = fmaxf(w1.x, 0.f); w1.y = fmaxf(w1.y, 0.f);
        }
        if (v0) *(float2*)(o0 + c) = w0;
        if (v1) *(float2*)(o1 + c) = w1;
    }
}

// ---------------- comb-fused head GEMM: A row r = [graph[r/32] (384) | oe[r] (128)] ----------
__global__ void __launch_bounds__(128) gemm_comb(
    const uint4* __restrict__ wf, const float* __restrict__ bias,
    float* __restrict__ out, int M) {
    const int lane = threadIdx.x & 31;
    const int warp = threadIdx.x >> 5;
    const int fr = lane >> 2;
    const int c2 = (lane & 3) * 2;
    const int rowBase = blockIdx.x * 64 + warp * 16;
    const int r0 = rowBase + fr;
    const int r1 = r0 + 8;
    const bool v0 = r0 < M, v1 = r1 < M;
    const uint4* wp = wf + lane;

    float acc[16][4];
#pragma unroll
    for (int t = 0; t < 16; t++)
#pragma unroll
        for (int i = 0; i < 4; i++) acc[t][i] = 0.f;

    const float2 z = make_float2(0.f, 0.f);
#pragma unroll 4
    for (int ks = 0; ks < 32; ks++) {
        int col = ks * 16 + c2;
        const float *a0p, *a1p;
        if (ks < 24) {   // graph region (chunk-aligned: 24*16 = 384)
            a0p = g_graph + (r0 >> 5) * 384 + col;
            a1p = g_graph + (r1 >> 5) * 384 + col;
        } else {         // oe region
            a0p = g_oe + (size_t)r0 * 128 + (col - 384);
            a1p = g_oe + (size_t)r1 * 128 + (col - 384);
        }
        float2 x00 = v0 ? __ldg((const float2*)a0p)       : z;
        float2 x10 = v1 ? __ldg((const float2*)a1p)       : z;
        float2 x02 = v0 ? __ldg((const float2*)(a0p + 8)) : z;
        float2 x12 = v1 ? __ldg((const float2*)(a1p + 8)) : z;
        uint32_t ah[4], al[4];
        cvt_hilo(x00, ah[0], al[0]);
        cvt_hilo(x10, ah[1], al[1]);
        cvt_hilo(x02, ah[2], al[2]);
        cvt_hilo(x12, ah[3], al[3]);
        const uint4* wk = wp + ks * 512;
#pragma unroll
        for (int nt = 0; nt < 16; nt++) {
            uint4 w = __ldg(wk + nt * 32);
            MMA_BF16(acc[nt], ah, w.x, w.y);
            MMA_BF16(acc[nt], ah, w.z, w.w);
            MMA_BF16(acc[nt], al, w.x, w.y);
        }
    }

    float* o0 = out + (size_t)r0 * 128;
    float* o1 = out + (size_t)r1 * 128;
#pragma unroll
    for (int nt = 0; nt < 16; nt++) {
        int c = nt * 8 + c2;
        float bx = __ldg(bias + c), by = __ldg(bias + c + 1);
        float2 w0 = make_float2(fmaxf(acc[nt][0] + bx, 0.f), fmaxf(acc[nt][1] + by, 0.f));
        float2 w1 = make_float2(fmaxf(acc[nt][2] + bx, 0.f), fmaxf(acc[nt][3] + by, 0.f));
        if (v0) *(float2*)(o0 + c) = w0;
        if (v1) *(float2*)(o1 + c) = w1;
    }
}

// ---------------- BN stats: column sum / sumsq (buffer pre-zeroed by gather block0) ------
__global__ void stats_k(const float* __restrict__ z, float* __restrict__ stats, int n) {
    __shared__ float ss[256], sq[256];
    int c = threadIdx.x & 127;
    int half = threadIdx.x >> 7;
    float s = 0.f, q = 0.f;
    for (int r = blockIdx.x * 2 + half; r < n; r += gridDim.x * 2) {
        float v = z[(size_t)r * 128 + c];
        s += v; q += v * v;
    }
    ss[threadIdx.x] = s; sq[threadIdx.x] = q;
    __syncthreads();
    if (threadIdx.x < 128) {
        atomicAdd(&stats[threadIdx.x], ss[threadIdx.x] + ss[threadIdx.x + 128]);
        atomicAdd(&stats[128 + threadIdx.x], sq[threadIdx.x] + sq[threadIdx.x + 128]);
    }
}

// ---------------- pooling with fused BN (no relu on last layer) ----------------
__global__ void pool_init_k(int B) {
    int i = blockIdx.x * blockDim.x + threadIdx.x;
    if (i < B * HD) { g_ssum[i] = 0.f; g_smax[i] = 0x007FFFFFu; }
    if (i < B) g_cnt[i] = 0;
}
__global__ void pool_k(const float* __restrict__ z, const int* __restrict__ batch,
                       const float* __restrict__ gamma, const float* __restrict__ beta,
                       const float* __restrict__ st, int n, float invN) {
    const int t = threadIdx.x;                // 128 threads, one per feature
    float mu = st[t] * invN;
    float q = st[128 + t] * invN;
    float var = q - mu * mu;
    float aa = gamma[t] * rsqrtf(var + 1e-5f);
    float bb = beta[t] - mu * aa;

    int start = blockIdx.x * 256;
    int end = min(start + 256, n);
    if (start >= end) return;
    int cur = __ldg(batch + start);
    float s = 0.f, m = NEG_INF;
    int c = 0;
    for (int v0 = start; v0 < end; v0 += 8) {
        float vals[8]; int bs[8];
        int mm = min(8, end - v0);
#pragma unroll
        for (int k = 0; k < 8; k++) {
            if (k < mm) {
                vals[k] = aa * __ldg(z + (size_t)(v0 + k) * HD + t) + bb;
                bs[k] = __ldg(batch + v0 + k);
            }
        }
        for (int k = 0; k < mm; k++) {
            if (bs[k] != cur) {
                atomicAdd(&g_ssum[cur * HD + t], s);
                atomicMax(&g_smax[cur * HD + t], fenc(m));
                if (t == 0) atomicAdd(&g_cnt[cur], c);
                cur = bs[k]; s = 0.f; m = NEG_INF; c = 0;
            }
            s += vals[k]; m = fmaxf(m, vals[k]); c++;
        }
    }
    atomicAdd(&g_ssum[cur * HD + t], s);
    atomicMax(&g_smax[cur * HD + t], fenc(m));
    if (t == 0) atomicAdd(&g_cnt[cur], c);
}
__global__ void graph_k(int B) {
    int i = blockIdx.x * blockDim.x + threadIdx.x;
    if (i >= B * 384) return;
    int b = i / 384, c = i % 384;
    float o;
    if (c < 128)      o = g_ssum[b * HD + c] / (float)max(g_cnt[b], 1);
    else if (c < 256) o = (g_cnt[b] == 0) ? 0.f : fdec(g_smax[b * HD + c - 128]);
    else              o = g_ssum[b * HD + (c - 256)];
    g_graph[i] = o;
}

// ---------------- SIMT GEMM NT=64 ----------------
template <int NT, bool RELU>
__global__ __launch_bounds__(2 * NT, 2)
void gemm_k(const float* __restrict__ A, const float* __restrict__ W,
            const float* __restrict__ bias, float* __restrict__ out, int M, int K) {
    constexpr int THREADS = 2 * NT;
    constexpr int TX = NT / 8;
    __shared__ float As[32][128];
    __shared__ float Bs[32][NT];
    const int tid = threadIdx.x;
    const int tx = tid % TX;
    const int ty = tid / TX;
    const int rowBase = blockIdx.x * 128;
    float acc[8][8];
#pragma unroll
    for (int j = 0; j < 8; j++)
#pragma unroll
        for (int i = 0; i < 8; i++) acc[j][i] = 0.f;
    for (int kt = 0; kt < K; kt += 32) {
#pragma unroll
        for (int q0 = 0; q0 < 1024 / THREADS; q0++) {
            int q = q0 * THREADS + tid;
            int r = q >> 3;
            int kq = (q & 7) * 4;
            float4 v = make_float4(0.f, 0.f, 0.f, 0.f);
            int gr = rowBase + r;
            if (gr < M) v = *(const float4*)(A + (size_t)gr * K + kt + kq);
            As[kq + 0][r] = v.x; As[kq + 1][r] = v.y;
            As[kq + 2][r] = v.z; As[kq + 3][r] = v.w;
        }
#pragma unroll
        for (int q0 = 0; q0 < (32 * NT / 4) / THREADS; q0++) {
            int q = q0 * THREADS + tid;
            int kl = q / (NT / 4);
            int c4 = (q % (NT / 4)) * 4;
            *(float4*)&Bs[kl][c4] = *(const float4*)(W + (size_t)(kt + kl) * NT + c4);
        }
        __syncthreads();
#pragma unroll
        for (int kl = 0; kl < 32; kl++) {
            float a[8], b[8];
            *(float4*)&a[0] = *(const float4*)&As[kl][ty * 8];
            *(float4*)&a[4] = *(const float4*)&As[kl][ty * 8 + 4];
            *(float4*)&b[0] = *(const float4*)&Bs[kl][tx * 8];
            *(float4*)&b[4] = *(const float4*)&Bs[kl][tx * 8 + 4];
#pragma unroll
            for (int j = 0; j < 8; j++)
#pragma unroll
                for (int i = 0; i < 8; i++)
                    acc[j][i] = fmaf(a[j], b[i], acc[j][i]);
        }
        __syncthreads();
    }
    float br[8];
#pragma unroll
    for (int i = 0; i < 8; i++) br[i] = __ldg(bias + tx * 8 + i);
#pragma unroll
    for (int j = 0; j < 8; j++) {
        int gr = rowBase + ty * 8 + j;
        if (gr >= M) continue;
        float v[8];
#pragma unroll
        for (int i = 0; i < 8; i++) {
            v[i] = acc[j][i] + br[i];
            if (RELU) v[i] = fmaxf(v[i], 0.f);
        }
        float* op = out + (size_t)gr * NT + tx * 8;
        *(float4*)op       = make_float4(v[0], v[1], v[2], v[3]);
        *(float4*)(op + 4) = make_float4(v[4], v[5], v[6], v[7]);
    }
}

// ---------------- final dot ----------------
__global__ void s3_k(const float* __restrict__ s2, const float* __restrict__ W,
                     const float* __restrict__ b, float* __restrict__ out, int rows) {
    int warp = (blockIdx.x * blockDim.x + threadIdx.x) >> 5;
    int lane = threadIdx.x & 31;
    if (warp >= rows) return;
    const float* row = s2 + (size_t)warp * 64;
    float s = row[lane] * W[lane] + row[lane + 32] * W[lane + 32];
#pragma unroll
    for (int o = 16; o > 0; o >>= 1) s += __shfl_down_sync(0xffffffffu, s, o);
    if (lane == 0) out[warp] = s + b[0];
}

// ---------------- launch ----------------
extern "C" void kernel_launch(void* const* d_in, const int* in_sizes, int n_in,
                              void* d_out, int out_size) {
    const float* x      = (const float*)d_in[0];
    const int*   ei     = (const int*)d_in[1];
    const float* orders = (const float*)d_in[2];
    const int*   batch  = (const int*)d_in[3];
    const float* gW1    = (const float*)d_in[4];
    const float* gb1    = (const float*)d_in[5];
    const float* gW2    = (const float*)d_in[6];
    const float* gb2    = (const float*)d_in[7];
    const float* gamma  = (const float*)d_in[8];
    const float* beta   = (const float*)d_in[9];
    const float* oW1    = (const float*)d_in[10];
    const float* ob1    = (const float*)d_in[11];
    const float* oW2    = (const float*)d_in[12];
    const float* ob2    = (const float*)d_in[13];
    const float* sW1    = (const float*)d_in[14];
    const float* sb1    = (const float*)d_in[15];
    const float* sW2    = (const float*)d_in[16];
    const float* sb2    = (const float*)d_in[17];
    const float* sW3    = (const float*)d_in[18];
    const float* sb3    = (const float*)d_in[19];
    float* out = (float*)d_out;

    const int n = in_sizes[0] / HD;
    const int E = in_sizes[1] / 2;
    const int B = in_sizes[2] / (OMAX * 32);
    const int L = in_sizes[4] / (HD * HD);
    const int rows = B * OMAX;
    const float invN = 1.0f / (float)n;

    float *zB, *aggB, *z1B, *statsB, *oeB, *s1B, *s2B;
    uint4* wfB;
    cudaGetSymbolAddress((void**)&zB, g_z);
    cudaGetSymbolAddress((void**)&aggB, g_agg);
    cudaGetSymbolAddress((void**)&z1B, g_z1);
    cudaGetSymbolAddress((void**)&statsB, g_stats);
    cudaGetSymbolAddress((void**)&oeB, g_oe);
    cudaGetSymbolAddress((void**)&s1B, g_s1);
    cudaGetSymbolAddress((void**)&s2B, g_s2);
    cudaGetSymbolAddress((void**)&wfB, g_wfrag);

    prep_k<<<720, 256>>>(gW1, gW2, oW1, oW2, sW1);

    // CSR build
    zero_deg_k<<<(n + 255) / 256, 256>>>(n);
    hist_k<<<(E + 255) / 256, 256>>>(ei, E);
    partial_k<<<256, 256>>>(n);
    scanb_k<<<1, 256>>>();
    rowptr_k<<<256, 256>>>(n, E);
    fill_k<<<(E + 255) / 256, 256>>>(ei, E);

    const int gGrid = (n + 63) / 64;
    for (int l = 0; l < L; l++) {
        const float* src = (l == 0) ? x : zB;
        int pl = (l > 0) ? (l - 1) : 0;
        float* stR = statsB + (pl & 1) * 256;   // prev layer's stats (read)
        float* stZ = statsB + (l & 1) * 256;    // this layer's stats buffer (zero)
        gather_k<<<(n + 7) / 8, 256>>>(src, aggB, gamma + pl * HD, beta + pl * HD,
                                       stR, stZ, n, l > 0, l > 0, invN);
        gemm_f<<<gGrid, 128>>>(aggB, wfB + (size_t)l * 4096, gb1 + l * HD,
                               z1B, n, HD, 1);
        gemm_f<<<gGrid, 128>>>(z1B, wfB + (size_t)(3 + l) * 4096, gb2 + l * HD,
                               zB, n, HD, 0);
        stats_k<<<1024, 256>>>(zB, stZ, n);
    }

    pool_init_k<<<(B * HD + 255) / 256, 256>>>(B);
    pool_k<<<(n + 255) / 256, 128>>>(zB, batch, gamma + (L - 1) * HD, beta + (L - 1) * HD,
                                     statsB + ((L - 1) & 1) * 256, n, invN);
    graph_k<<<(B * 384 + 255) / 256, 256>>>(B);

    const int hGrid = (rows + 63) / 64;
    gemm_f<<<hGrid, 128>>>(orders, wfB + 24576, ob1, z1B, rows, 32, 1);
    gemm_f<<<hGrid, 128>>>(z1B, wfB + 25600, ob2, oeB, rows, HD, 0);
    gemm_comb<<<hGrid, 128>>>(wfB + 29696, sb1, s1B, rows);
    gemm_k<64, true><<<(rows + 127) / 128, 128>>>(s1B, sW2, sb2, s2B, rows, HD);
    s3_k<<<(rows + 7) / 8, 256>>>(s2B, sW3, sb3, out, rows);
}